// round 1
// baseline (speedup 1.0000x reference)
#include <cuda_runtime.h>
#include <math.h>

#define HH 256
#define NP 32
#define LL 8192
#define LH 4097           // L/2 + 1
#define M2 4096           // L/2  (packed real-IFFT size)

#ifndef PI_D
#define PI_D 3.14159265358979323846
#endif

// scratch: k_f spectrum, one row per head (complex)
__device__ float2 g_kf[HH * LH];

// ---------------------------------------------------------------------------
// Kernel A: Cauchy sums + Woodbury correction -> k_f[h][l]
// grid = (ceil(LH/512), H), block = 512, one thread per frequency node l.
// ---------------------------------------------------------------------------
__global__ __launch_bounds__(512) void cauchy_kernel(
    const float* __restrict__ w_re, const float* __restrict__ w_im,
    const float* __restrict__ p_re, const float* __restrict__ p_im,
    const float* __restrict__ B_re, const float* __restrict__ B_im,
    const float* __restrict__ C_re, const float* __restrict__ C_im,
    const float* __restrict__ log_dt)
{
    __shared__ float4 sh[NP * 3];
    __shared__ float sh_dt;

    const int h   = blockIdx.y;
    const int tid = threadIdx.x;

    if (tid < NP) {
        const float dt = expf(log_dt[h]);
        if (tid == 0) sh_dt = dt;
        const int idx = h * NP + tid;
        const float a  = w_re[idx] * dt;      // fold dt into pole (w * dt)
        const float b  = w_im[idx] * dt;
        const float Br = B_re[idx], Bi = B_im[idx];
        const float Pr = p_re[idx], Pi = p_im[idx];
        const float Cr = C_re[idx], Ci = C_im[idx];
        // v00 = B*C, v01 = B*conj(P), v10 = P*C, v11 = |P|^2 (real)
        sh[tid * 3 + 0] = make_float4(a, a * a, b, Pr * Pr + Pi * Pi);
        sh[tid * 3 + 1] = make_float4(Br * Cr - Bi * Ci,  // v00r
                                      Br * Ci + Bi * Cr,  // v00i
                                      Br * Pr + Bi * Pi,  // v01r
                                      Bi * Pr - Br * Pi); // v01i
        sh[tid * 3 + 2] = make_float4(Pr * Cr - Pi * Ci,  // v10r
                                      Pr * Ci + Pi * Cr,  // v10i
                                      0.f, 0.f);
    }
    __syncthreads();

    const int l = blockIdx.x * blockDim.x + tid;
    if (l >= LH) return;

    // z = i*y with y = 2*tan(pi*l/L)  (double for accuracy near l = L/2)
    const float y = (float)(2.0 * tan((PI_D / (double)LL) * (double)l));

    float r00r = 0.f, r00i = 0.f, r01r = 0.f, r01i = 0.f;
    float r10r = 0.f, r10i = 0.f, r11r = 0.f, r11i = 0.f;

#pragma unroll
    for (int n = 0; n < NP; n++) {
        const float4 pa = sh[n * 3 + 0];
        const float4 v0 = sh[n * 3 + 1];
        const float4 v1 = sh[n * 3 + 2];
        const float a = pa.x, a2 = pa.y, b = pa.z, v11 = pa.w;
        // cw = 1/(z - w) = 1/(-a, y-b) ; cwc = 1/(z - conj w) = 1/(-a, y+b)
        const float t1 = y - b;
        const float t2 = y + b;
        const float inv1 = __frcp_rn(fmaf(t1, t1, a2));
        const float inv2 = __frcp_rn(fmaf(t2, t2, a2));
        const float u1 = t1 * inv1;
        const float u2 = t2 * inv2;
        // combined conj-pair coefficients:
        // term_r = vr*Sr + vi*Di ; term_i = vr*Si + vi*Dr
        const float Sr = -a * (inv1 + inv2);
        const float Dr =  a * (inv2 - inv1);
        const float Si = -(u1 + u2);
        const float Di =  u1 - u2;

        r00r = fmaf(v0.x, Sr, fmaf(v0.y, Di, r00r));
        r00i = fmaf(v0.x, Si, fmaf(v0.y, Dr, r00i));
        r01r = fmaf(v0.z, Sr, fmaf(v0.w, Di, r01r));
        r01i = fmaf(v0.z, Si, fmaf(v0.w, Dr, r01i));
        r10r = fmaf(v1.x, Sr, fmaf(v1.y, Di, r10r));
        r10i = fmaf(v1.x, Si, fmaf(v1.y, Dr, r10i));
        r11r = fmaf(v11, Sr, r11r);
        r11i = fmaf(v11, Si, r11i);
    }

    const float dt = sh_dt;
    r00r *= dt; r00i *= dt;
    r01r *= dt; r01i *= dt;
    r10r *= dt; r10i *= dt;
    r11r *= dt; r11i *= dt;

    // Woodbury: k_f = (r00 - r01*r10/(1+r11)) * (1 + i*y/2)
    const float dr = 1.f + r11r;
    const float di = r11i;
    const float invd = __frcp_rn(fmaf(dr, dr, di * di));
    const float numr = r01r * r10r - r01i * r10i;
    const float numi = r01r * r10i + r01i * r10r;
    const float cr = (numr * dr + numi * di) * invd;
    const float ci = (numi * dr - numr * di) * invd;
    const float ar = r00r - cr;
    const float ai = r00i - ci;
    const float g = 0.5f * y;                 // 2/(1+omega) = 1 + i*g
    g_kf[h * LH + l] = make_float2(fmaf(-ai, g, ar), fmaf(ar, g, ai));
}

// ---------------------------------------------------------------------------
// Kernel B: irfft(k_f) per head via packed real-IFFT (4096-pt complex DIT FFT
// in shared memory). grid = H blocks, 512 threads, 48 KB dynamic shared.
// ---------------------------------------------------------------------------
__global__ __launch_bounds__(512) void ifft_kernel(float* __restrict__ out)
{
    extern __shared__ float2 shm[];
    float2* spec = shm;            // 4096 complex  (32 KB)
    float2* tw   = shm + M2;       // 2048 twiddles (16 KB): e^{+2*pi*i*t/4096}

    const int h   = blockIdx.x;
    const int tid = threadIdx.x;

    for (int t = tid; t < M2 / 2; t += blockDim.x) {
        float s, c;
        sincosf((float)((2.0 * PI_D / (double)M2) * (double)t), &s, &c);
        tw[t] = make_float2(c, s);
    }

    // Pack Hermitian half-spectrum X[0..4096] into Zf[0..4095] (bit-reversed).
    // Ek = (X[k] + conj(X[M-k]))/2 ; Ok = e^{+2*pi*i*k/L} * (X[k]-conj(X[M-k]))/2
    // Zf[k] = E + i*O ; Zf[M-k] = conj(E - i*O)
    const float2* kf = g_kf + h * LH;
    for (int k = tid; k <= M2 / 2; k += blockDim.x) {
        const float2 Xk = kf[k];
        const float2 Xm = kf[M2 - k];
        const float mr = Xm.x, mi = -Xm.y;            // conj(X[M-k])
        const float Er = 0.5f * (Xk.x + mr);
        const float Ei = 0.5f * (Xk.y + mi);
        const float Fr = 0.5f * (Xk.x - mr);
        const float Fi = 0.5f * (Xk.y - mi);
        float s, c;
        sincosf((float)((PI_D / (double)M2) * (double)k), &s, &c); // e^{+2*pi*i*k/L}
        const float Or = c * Fr - s * Fi;
        const float Oi = c * Fi + s * Fr;
        spec[__brev((unsigned)k) >> 20] = make_float2(Er - Oi, Ei + Or);
        if (k > 0 && k < M2 / 2) {
            spec[__brev((unsigned)(M2 - k)) >> 20] = make_float2(Er + Oi, Or - Ei);
        }
    }
    __syncthreads();

    // In-place radix-2 DIT inverse FFT (twiddles already e^{+i...}), 12 stages.
#pragma unroll 1
    for (int s = 1; s <= 12; s++) {
        const int half = 1 << (s - 1);
        const int tsh  = 12 - s;
        for (int j = tid; j < M2 / 2; j += blockDim.x) {
            const int pos = j & (half - 1);
            const int i1  = ((j >> (s - 1)) << s) | pos;
            const int i2  = i1 + half;
            const float2 w = tw[pos << tsh];
            const float2 xa = spec[i1];
            const float2 xb = spec[i2];
            const float trm = xb.x * w.x - xb.y * w.y;
            const float tim = xb.x * w.y + xb.y * w.x;
            spec[i1] = make_float2(xa.x + trm, xa.y + tim);
            spec[i2] = make_float2(xa.x - trm, xa.y - tim);
        }
        __syncthreads();
    }

    // z[t] = x[2t] + i*x[2t+1], scale 1/M. Coalesced float2 stores.
    const float scale = 1.0f / (float)M2;
    float2* outv = (float2*)out + h * M2;
    for (int t = tid; t < M2; t += blockDim.x) {
        const float2 z = spec[t];
        outv[t] = make_float2(z.x * scale, z.y * scale);
    }
}

// ---------------------------------------------------------------------------
extern "C" void kernel_launch(void* const* d_in, const int* in_sizes, int n_in,
                              void* d_out, int out_size)
{
    const float* w_re   = (const float*)d_in[0];
    const float* w_im   = (const float*)d_in[1];
    const float* p_re   = (const float*)d_in[2];
    const float* p_im   = (const float*)d_in[3];
    const float* B_re   = (const float*)d_in[4];
    const float* B_im   = (const float*)d_in[5];
    const float* C_re   = (const float*)d_in[6];
    const float* C_im   = (const float*)d_in[7];
    const float* log_dt = (const float*)d_in[8];
    // d_in[9] is L (compile-time constant 8192 here)

    dim3 gridA((LH + 511) / 512, HH);
    cauchy_kernel<<<gridA, 512>>>(w_re, w_im, p_re, p_im,
                                  B_re, B_im, C_re, C_im, log_dt);

    ifft_kernel<<<HH, 512, (M2 + M2 / 2) * sizeof(float2)>>>((float*)d_out);
}

// round 3
// speedup vs baseline: 1.3332x; 1.3332x over previous
#include <cuda_runtime.h>
#include <math.h>

#define HH 256
#define NP 32
#define LL 8192
#define LH 4097           // L/2 + 1
#define M2 4096           // L/2  (packed real-IFFT size)
#define ROW 4098          // padded k_f row stride (keeps rows 16B-aligned)

#ifndef PI_D
#define PI_D 3.14159265358979323846
#endif

// scratch: k_f spectrum, one padded row per head (complex)
__device__ float2 g_kf[HH * ROW];

// ---------------- packed f32x2 helpers (sm_100+) ----------------
typedef unsigned long long u64;

__device__ __forceinline__ u64 pk2(float lo, float hi) {
    u64 r; asm("mov.b64 %0, {%1,%2};" : "=l"(r) : "f"(lo), "f"(hi)); return r;
}
__device__ __forceinline__ void upk2(u64 v, float& lo, float& hi) {
    asm("mov.b64 {%0,%1}, %2;" : "=f"(lo), "=f"(hi) : "l"(v));
}
__device__ __forceinline__ u64 fma2(u64 a, u64 b, u64 c) {
    u64 d; asm("fma.rn.f32x2 %0,%1,%2,%3;" : "=l"(d) : "l"(a), "l"(b), "l"(c)); return d;
}
__device__ __forceinline__ u64 add2(u64 a, u64 b) {
    u64 d; asm("add.rn.f32x2 %0,%1,%2;" : "=l"(d) : "l"(a), "l"(b)); return d;
}
__device__ __forceinline__ u64 mul2(u64 a, u64 b) {
    u64 d; asm("mul.rn.f32x2 %0,%1,%2;" : "=l"(d) : "l"(a), "l"(b)); return d;
}
__device__ __forceinline__ u64 rcp2(u64 a) {
    float lo, hi, rl, rh;
    upk2(a, lo, hi);
    asm("rcp.approx.f32 %0,%1;" : "=f"(rl) : "f"(lo));
    asm("rcp.approx.f32 %0,%1;" : "=f"(rh) : "f"(hi));
    return pk2(rl, rh);
}

// y = 2*tan(pi*l/L); double path near the Nyquist pole where float arg error
// is amplified by 1/(pi/2 - x).
__device__ __forceinline__ float y_of(int l) {
    if (l >= LH) l = LH - 1;                 // dummy hi-lane of the last pair
    if (l < 3968) return 2.0f * tanf((float)l * (float)(PI_D / (double)LL));
    return (float)(2.0 * tan((PI_D / (double)LL) * (double)l));
}

// ---------------------------------------------------------------------------
// Kernel A: Cauchy sums + Woodbury -> k_f[h][l], two nodes per thread (f32x2)
// grid = (9, H), block = 256.
// ---------------------------------------------------------------------------
__global__ __launch_bounds__(256) void cauchy_kernel(
    const float* __restrict__ w_re, const float* __restrict__ w_im,
    const float* __restrict__ p_re, const float* __restrict__ p_im,
    const float* __restrict__ B_re, const float* __restrict__ B_im,
    const float* __restrict__ C_re, const float* __restrict__ C_im,
    const float* __restrict__ log_dt)
{
    // per-pole packed constants, each ulonglong2 = two f32x2 pairs
    __shared__ ulonglong2 sh[NP][6];
    __shared__ float sh_dt;

    const int h   = blockIdx.y;
    const int tid = threadIdx.x;

    if (tid < NP) {
        const float dt = expf(log_dt[h]);
        if (tid == 0) sh_dt = dt;
        const int idx = h * NP + tid;
        const float a  = w_re[idx] * dt;      // fold dt into pole
        const float b  = w_im[idx] * dt;
        const float Br = B_re[idx], Bi = B_im[idx];
        const float Pr = p_re[idx], Pi = p_im[idx];
        const float Cr = C_re[idx], Ci = C_im[idx];
        const float v00r = Br * Cr - Bi * Ci, v00i = Br * Ci + Bi * Cr;  // B*C
        const float v01r = Br * Pr + Bi * Pi, v01i = Bi * Pr - Br * Pi;  // B*conj(P)
        const float v10r = Pr * Cr - Pi * Ci, v10i = Pr * Ci + Pi * Cr;  // P*C
        const float v11  = Pr * Pr + Pi * Pi;                            // |P|^2 (real)
        sh[tid][0] = make_ulonglong2(pk2(a * a, a * a), pk2(b, b));
        sh[tid][1] = make_ulonglong2(pk2(-b, -b),      pk2(a, a));
        sh[tid][2] = make_ulonglong2(pk2(-a, -a),      pk2(v11, v11));
        sh[tid][3] = make_ulonglong2(pk2(v00r, v00r),  pk2(v00i, v00i));
        sh[tid][4] = make_ulonglong2(pk2(v01r, v01r),  pk2(v01i, v01i));
        sh[tid][5] = make_ulonglong2(pk2(v10r, v10r),  pk2(v10i, v10i));
    }
    __syncthreads();

    const int t  = blockIdx.x * blockDim.x + tid;   // pair index
    const int l0 = 2 * t;
    if (l0 >= LH) return;

    const float y0 = y_of(l0);
    const float y1 = y_of(l0 + 1);      // clamped dummy when l0+1 == LH
    const u64 yy = pk2(y0, y1);
    const u64 m1 = pk2(-1.0f, -1.0f);

    u64 r00r = 0, r00i = 0, r01r = 0, r01i = 0, r10r = 0, r10i = 0, r11r = 0, r11i = 0;

#pragma unroll
    for (int n = 0; n < NP; n++) {
        const ulonglong2 e0 = sh[n][0];   // a2 | b
        const ulonglong2 e1 = sh[n][1];   // -b | a
        const ulonglong2 e2 = sh[n][2];   // -a | v11
        const ulonglong2 e3 = sh[n][3];   // v00r | v00i
        const ulonglong2 e4 = sh[n][4];   // v01r | v01i
        const ulonglong2 e5 = sh[n][5];   // v10r | v10i

        const u64 t1 = add2(yy, e1.x);                 // y - b
        const u64 t2 = add2(yy, e0.y);                 // y + b
        const u64 inv1 = rcp2(fma2(t1, t1, e0.x));     // 1/(t1^2 + a^2)
        const u64 inv2 = rcp2(fma2(t2, t2, e0.x));
        const u64 u1 = mul2(t1, inv1);
        const u64 u2 = mul2(t2, inv2);
        const u64 Sr = mul2(e2.x, add2(inv1, inv2));   // -a*(inv1+inv2)
        const u64 Dr = mul2(e1.y, fma2(inv1, m1, inv2)); //  a*(inv2-inv1)
        const u64 Si = mul2(add2(u1, u2), m1);         // -(u1+u2)
        const u64 Di = fma2(u2, m1, u1);               //  u1-u2

        r00r = fma2(e3.x, Sr, fma2(e3.y, Di, r00r));
        r00i = fma2(e3.x, Si, fma2(e3.y, Dr, r00i));
        r01r = fma2(e4.x, Sr, fma2(e4.y, Di, r01r));
        r01i = fma2(e4.x, Si, fma2(e4.y, Dr, r01i));
        r10r = fma2(e5.x, Sr, fma2(e5.y, Di, r10r));
        r10i = fma2(e5.x, Si, fma2(e5.y, Dr, r10i));
        r11r = fma2(e2.y, Sr, r11r);
        r11i = fma2(e2.y, Si, r11i);
    }

    const float dt = sh_dt;
    float a00r[2], a00i[2], a01r[2], a01i[2], a10r[2], a10i[2], a11r[2], a11i[2];
    upk2(r00r, a00r[0], a00r[1]); upk2(r00i, a00i[0], a00i[1]);
    upk2(r01r, a01r[0], a01r[1]); upk2(r01i, a01i[0], a01i[1]);
    upk2(r10r, a10r[0], a10r[1]); upk2(r10i, a10i[0], a10i[1]);
    upk2(r11r, a11r[0], a11r[1]); upk2(r11i, a11i[0], a11i[1]);

    float2 res[2];
    const float yv[2] = {y0, y1};
#pragma unroll
    for (int s = 0; s < 2; s++) {
        const float q00r = a00r[s] * dt, q00i = a00i[s] * dt;
        const float q01r = a01r[s] * dt, q01i = a01i[s] * dt;
        const float q10r = a10r[s] * dt, q10i = a10i[s] * dt;
        const float q11r = a11r[s] * dt, q11i = a11i[s] * dt;
        // Woodbury: k_f = (r00 - r01*r10/(1+r11)) * (1 + i*y/2)
        const float dr = 1.f + q11r, di = q11i;
        float invd; asm("rcp.approx.f32 %0,%1;" : "=f"(invd) : "f"(fmaf(dr, dr, di * di)));
        const float numr = q01r * q10r - q01i * q10i;
        const float numi = q01r * q10i + q01i * q10r;
        const float cr = (numr * dr + numi * di) * invd;
        const float ci = (numi * dr - numr * di) * invd;
        const float ar = q00r - cr, ai = q00i - ci;
        const float g = 0.5f * yv[s];
        res[s] = make_float2(fmaf(-ai, g, ar), fmaf(ar, g, ai));
    }

    float2* row = g_kf + h * ROW;
    if (l0 + 1 < LH) {
        *reinterpret_cast<float4*>(row + l0) =
            make_float4(res[0].x, res[0].y, res[1].x, res[1].y);
    } else {
        row[l0] = res[0];            // l0 == 4096 tail
    }
}

// ---------------------------------------------------------------------------
// helpers for the FFT
// ---------------------------------------------------------------------------
__device__ __forceinline__ float2 cmul(float2 a, float2 b) {
    return make_float2(a.x * b.x - a.y * b.y, a.x * b.y + a.y * b.x);
}
__device__ __forceinline__ int dr4(int k) {   // base-4 digit reversal of 12-bit index
    unsigned r = __brev((unsigned)k) >> 20;
    return (int)(((r & 0x555u) << 1) | ((r >> 1) & 0x555u));
}

// ---------------------------------------------------------------------------
// Kernel B: irfft(k_f) per head via packed real-IFFT, radix-4 DIT in shared.
// grid = H blocks, 512 threads, 48 KB dynamic shared.
// ---------------------------------------------------------------------------
__global__ __launch_bounds__(512) void ifft_kernel(float* __restrict__ out)
{
    extern __shared__ float2 shm[];
    float2* spec = shm;            // 4096 complex  (32 KB)
    float2* tw   = shm + M2;       // 2048 twiddles (16 KB): e^{+2*pi*i*t/4096}

    const int h   = blockIdx.x;
    const int tid = threadIdx.x;

    for (int t = tid; t < M2 / 2; t += blockDim.x) {
        float s, c;
        sincosf((float)((2.0 * PI_D / (double)M2) * (double)t), &s, &c);
        tw[t] = make_float2(c, s);
    }

    // Hermitian pack with 1/M scale folded in, base-4 digit-reversed layout.
    const float sc = 0.5f / (float)M2;
    const float2* kf = g_kf + h * ROW;
    for (int k = tid; k <= M2 / 2; k += blockDim.x) {
        const float2 Xk = kf[k];
        const float2 Xm = kf[M2 - k];
        const float mr = Xm.x, mi = -Xm.y;            // conj(X[M-k])
        const float Er = sc * (Xk.x + mr);
        const float Ei = sc * (Xk.y + mi);
        const float Fr = sc * (Xk.x - mr);
        const float Fi = sc * (Xk.y - mi);
        float s, c;
        sincosf((float)((PI_D / (double)M2) * (double)k), &s, &c); // e^{+2*pi*i*k/L}
        const float Or = c * Fr - s * Fi;
        const float Oi = c * Fi + s * Fr;
        spec[dr4(k)] = make_float2(Er - Oi, Ei + Or);
        if (k > 0 && k < M2 / 2) {
            spec[dr4(M2 - k)] = make_float2(Er + Oi, Or - Ei);
        }
    }
    __syncthreads();

    // Stage 0 (q = 1): all twiddles are 1.
    for (int j = tid; j < M2 / 4; j += blockDim.x) {
        const int i0 = j << 2;
        const float2 x0 = spec[i0], x1 = spec[i0 + 1], x2 = spec[i0 + 2], x3 = spec[i0 + 3];
        const float apx = x0.x + x2.x, apy = x0.y + x2.y;
        const float amx = x0.x - x2.x, amy = x0.y - x2.y;
        const float bpx = x1.x + x3.x, bpy = x1.y + x3.y;
        const float bmx = x1.x - x3.x, bmy = x1.y - x3.y;
        spec[i0]     = make_float2(apx + bpx, apy + bpy);
        spec[i0 + 1] = make_float2(amx - bmy, amy + bmx);   // am + i*bm
        spec[i0 + 2] = make_float2(apx - bpx, apy - bpy);
        spec[i0 + 3] = make_float2(amx + bmy, amy - bmx);   // am - i*bm
    }
    __syncthreads();

    // Stages 1..5: q = 4, 16, 64, 256, 1024.
#pragma unroll 1
    for (int st = 1; st < 6; st++) {
        const int q    = 1 << (2 * st);
        const int tsh  = 10 - 2 * st;       // twiddle stride shift: 1024/q
        for (int j = tid; j < M2 / 4; j += blockDim.x) {
            const int pos = j & (q - 1);
            const int i0  = ((j >> (2 * st)) << (2 * st + 2)) | pos;
            const int tb  = pos << tsh;
            const float2 w1 = tw[tb];
            const float2 w2 = tw[2 * tb];
            const float2 w3 = cmul(w1, w2);
            const float2 x0 = spec[i0];
            const float2 b  = cmul(spec[i0 + q],     w1);
            const float2 c  = cmul(spec[i0 + 2 * q], w2);
            const float2 d  = cmul(spec[i0 + 3 * q], w3);
            const float apx = x0.x + c.x, apy = x0.y + c.y;
            const float amx = x0.x - c.x, amy = x0.y - c.y;
            const float bpx = b.x + d.x,  bpy = b.y + d.y;
            const float bmx = b.x - d.x,  bmy = b.y - d.y;
            spec[i0]         = make_float2(apx + bpx, apy + bpy);
            spec[i0 + q]     = make_float2(amx - bmy, amy + bmx);
            spec[i0 + 2 * q] = make_float2(apx - bpx, apy - bpy);
            spec[i0 + 3 * q] = make_float2(amx + bmy, amy - bmx);
        }
        __syncthreads();
    }

    // z[t] = x[2t] + i*x[2t+1], already scaled. Coalesced float2 stores.
    float2* outv = (float2*)out + h * M2;
    for (int t = tid; t < M2; t += blockDim.x) {
        outv[t] = spec[t];
    }
}

// ---------------------------------------------------------------------------
extern "C" void kernel_launch(void* const* d_in, const int* in_sizes, int n_in,
                              void* d_out, int out_size)
{
    const float* w_re   = (const float*)d_in[0];
    const float* w_im   = (const float*)d_in[1];
    const float* p_re   = (const float*)d_in[2];
    const float* p_im   = (const float*)d_in[3];
    const float* B_re   = (const float*)d_in[4];
    const float* B_im   = (const float*)d_in[5];
    const float* C_re   = (const float*)d_in[6];
    const float* C_im   = (const float*)d_in[7];
    const float* log_dt = (const float*)d_in[8];

    dim3 gridA(9, HH);      // 9*256 = 2304 >= 2049 node-pairs per head
    cauchy_kernel<<<gridA, 256>>>(w_re, w_im, p_re, p_im,
                                  B_re, B_im, C_re, C_im, log_dt);

    ifft_kernel<<<HH, 512, (M2 + M2 / 2) * sizeof(float2)>>>((float*)d_out);
}